// round 17
// baseline (speedup 1.0000x reference)
#include <cuda_runtime.h>
#include <cstdint>

// Problem constants
#define N_NODES 16384
#define KNBR    32
#define DIN     256
#define DOUT    256
#define DCAT    512
#define NROWS   (N_NODES * KNBR)   // 524288

// ---------------------------------------------------------------------------
// Arch gating: tcgen05 exists only under arch-SPECIFIC (sm_103a) compilation.
// The plain compute_103 PTX pass compiles slow-but-correct fallback bodies.
// ---------------------------------------------------------------------------
#if defined(__CUDA_ARCH__) && \
    (defined(__CUDA_ARCH_FEAT_SM103_ALL) || defined(__CUDA_ARCH_FEAT_SM100_ALL) || \
     (defined(__CUDA_ARCH_SPECIFIC__) && (__CUDA_ARCH_SPECIFIC__ >= 1000)))
#define HAS_TC 1
#else
#define HAS_TC 0
#endif

// ---------------------------------------------------------------------------
// Scratch (static device globals — no runtime allocation).
// Packed weights: chunk-major swizzled SMEM images (chunk = 32 K-cols;
// element (r, q) of a chunk at byte sw128(r*128 + q*16)).
// ---------------------------------------------------------------------------
__device__ float g_Q[N_NODES * DOUT];
__device__ float g_ctx[N_NODES * DOUT];
__device__ float g_ob[N_NODES * DCAT];
__device__ __align__(128) float g_Wqio_pk[DCAT * DIN];   // [Wq;Wio] packed
__device__ __align__(128) float g_Wkv_pk[DCAT * DIN];    // [Wk;Wv] packed
__device__ __align__(128) float g_Wno_pk[DOUT * DOUT];
__device__ __align__(128) float g_Wg_pk[DCAT * DCAT];
__device__ float g_psum[256 * DCAT];
__device__ float g_psq[256 * DCAT];
__device__ float g_mean[DCAT];
__device__ float g_rstd[DCAT];

// ---------------------------------------------------------------------------
// Helpers (arch-neutral)
// ---------------------------------------------------------------------------
__device__ __forceinline__ uint32_t smem_u32(const void* p) {
    uint32_t a;
    asm("{ .reg .u64 t; cvta.to.shared.u64 t, %1; cvt.u32.u64 %0, t; }" : "=r"(a) : "l"(p));
    return a;
}
__device__ __forceinline__ uint32_t rna_tf32(float f) {
    uint32_t r;
    asm("cvt.rna.tf32.f32 %0, %1;" : "=r"(r) : "f"(f));
    return r;
}
__device__ __forceinline__ uint32_t sw128(uint32_t off) { return off ^ ((off >> 3) & 0x70); }

// Read element (r, k) of a packed weight image with ntot rows
__device__ __forceinline__ float w_packed(const float* Wp, int ntot, int r, int k) {
    return Wp[(size_t)(k >> 5) * ((size_t)ntot * 32) +
              (sw128((uint32_t)((r << 7) + ((k & 31) << 2))) >> 2)];
}

#if HAS_TC
// ---------------------------------------------------------------------------
// tcgen05 / async / cluster helpers (compiled only for sm_10xa)
// ---------------------------------------------------------------------------
__device__ __forceinline__ uint32_t elect_one() {
    uint32_t p;
    asm volatile("{ .reg .pred P; elect.sync _|P, 0xFFFFFFFF; selp.b32 %0, 1, 0, P; }" : "=r"(p));
    return p;
}
__device__ __forceinline__ uint32_t cluster_rank() {
    uint32_t r;
    asm("mov.u32 %0, %%cluster_ctarank;" : "=r"(r));
    return r;
}
#define CLUSTER_SYNC() do { \
    asm volatile("barrier.cluster.arrive.aligned;" ::: "memory"); \
    asm volatile("barrier.cluster.wait.aligned;" ::: "memory"); \
} while (0)

#define TCGEN05_ALLOC(a, n) \
    asm volatile("tcgen05.alloc.cta_group::1.sync.aligned.shared::cta.b32 [%0], %1;" \
                 :: "r"(a), "r"(n) : "memory")
#define TCGEN05_DEALLOC(t, n) \
    asm volatile("tcgen05.dealloc.cta_group::1.sync.aligned.b32 %0, %1;" :: "r"(t), "r"(n))
#define TCGEN05_RELINQ() \
    asm volatile("tcgen05.relinquish_alloc_permit.cta_group::1.sync.aligned;")
#define TCGEN05_COMMIT(m) \
    asm volatile("tcgen05.commit.cta_group::1.mbarrier::arrive::one.shared::cluster.b64 [%0];" \
                 :: "r"(m) : "memory")
#define TCGEN05_COMMIT_MC(m, mask) \
    asm volatile("tcgen05.commit.cta_group::1.mbarrier::arrive::one.shared::cluster.multicast::cluster.b64 [%0], %1;" \
                 :: "r"(m), "h"((uint16_t)(mask)) : "memory")
#define TCGEN05_FENCE_AFTER()  asm volatile("tcgen05.fence::after_thread_sync;" ::: "memory")
#define TCGEN05_FENCE_BEFORE() asm volatile("tcgen05.fence::before_thread_sync;" ::: "memory")
#define TCGEN05_WAIT_LD()      asm volatile("tcgen05.wait::ld.sync.aligned;" ::: "memory")
#define MBARRIER_INIT(m, c) \
    asm volatile("mbarrier.init.shared.b64 [%0], %1;" :: "r"(m), "r"(c) : "memory")
#define MBARRIER_EXPECT_TX(m, b) \
    asm volatile("mbarrier.arrive.expect_tx.shared.b64 _, [%0], %1;" :: "r"(m), "r"(b) : "memory")
#define CP_ASYNC_BULK_G2S(dst, src, bytes, mbar) \
    asm volatile("cp.async.bulk.shared::cluster.global.mbarrier::complete_tx::bytes " \
                 "[%0], [%1], %2, [%3];" \
                 :: "r"(dst), "l"(src), "r"(bytes), "r"(mbar) : "memory")
#define CP_ASYNC_BULK_G2S_MC(dst, src, bytes, mbar, mask) \
    asm volatile("cp.async.bulk.shared::cluster.global.mbarrier::complete_tx::bytes.multicast::cluster " \
                 "[%0], [%1], %2, [%3], %4;" \
                 :: "r"(dst), "l"(src), "r"(bytes), "r"(mbar), "h"((uint16_t)(mask)) : "memory")

#define MBARRIER_WAIT_PARITY(mbar_smem_addr, phase_parity) do { \
    uint32_t _mbar = (uint32_t)(mbar_smem_addr); \
    uint32_t _parity = (uint32_t)(phase_parity); \
    uint32_t _done; \
    asm volatile( \
        "{\n\t" \
        ".reg .pred p;\n\t" \
        "mbarrier.try_wait.parity.acquire.cta.shared::cta.b64 p, [%1], %2;\n\t" \
        "selp.b32 %0, 1, 0, p;\n\t" \
        "}" \
        : "=r"(_done) : "r"(_mbar), "r"(_parity) : "memory"); \
    if (!_done) { \
        asm volatile( \
            "{\n\t" \
            ".reg .pred P1;\n\t" \
            "WAIT_LOOP_%=:\n\t" \
            "mbarrier.try_wait.parity.acquire.cta.shared::cta.b64 P1, [%0], %1, 0x989680;\n\t" \
            "@P1 bra.uni WAIT_DONE_%=;\n\t" \
            "bra.uni WAIT_LOOP_%=;\n\t" \
            "WAIT_DONE_%=:\n\t" \
            "}" \
            :: "r"(_mbar), "r"(_parity) : "memory"); \
    } \
} while (0)

#define TCGEN05_LD_32X32B_X32(r, tmem_addr) \
    asm volatile( \
        "tcgen05.ld.sync.aligned.32x32b.x32.b32 " \
        "{%0, %1, %2, %3, %4, %5, %6, %7, " \
        " %8, %9, %10, %11, %12, %13, %14, %15, " \
        " %16, %17, %18, %19, %20, %21, %22, %23, " \
        " %24, %25, %26, %27, %28, %29, %30, %31}, [%32];" \
        : "=r"((r)[0]),  "=r"((r)[1]),  "=r"((r)[2]),  "=r"((r)[3]), \
          "=r"((r)[4]),  "=r"((r)[5]),  "=r"((r)[6]),  "=r"((r)[7]), \
          "=r"((r)[8]),  "=r"((r)[9]),  "=r"((r)[10]), "=r"((r)[11]), \
          "=r"((r)[12]), "=r"((r)[13]), "=r"((r)[14]), "=r"((r)[15]), \
          "=r"((r)[16]), "=r"((r)[17]), "=r"((r)[18]), "=r"((r)[19]), \
          "=r"((r)[20]), "=r"((r)[21]), "=r"((r)[22]), "=r"((r)[23]), \
          "=r"((r)[24]), "=r"((r)[25]), "=r"((r)[26]), "=r"((r)[27]), \
          "=r"((r)[28]), "=r"((r)[29]), "=r"((r)[30]), "=r"((r)[31]) \
        : "r"(tmem_addr))

// SW128 K-major SMEM descriptor (LBO=1, SBO=64, version=1, layout=SW128)
__device__ __forceinline__ uint64_t sw128_desc(uint32_t addr) {
    constexpr uint64_t base = (2ull << 61) | (1ull << 46) | (64ull << 32) | (1ull << 16);
    return base | ((uint64_t)(addr >> 4) & 0x3FFFull);
}

// tcgen05 tf32 SS MMA: D[M=128, N=256] += A(smem desc) * B(smem desc)^T
__device__ __forceinline__ void mma_tf32_ss(uint32_t d, uint64_t ad, uint64_t bd,
                                            uint32_t idesc, uint32_t acc) {
    asm volatile(
        "{\n\t"
        ".reg .pred p;\n\t"
        "setp.ne.u32 p, %4, 0;\n\t"
        "tcgen05.mma.cta_group::1.kind::tf32 [%0], %1, %2, %3, p;\n\t"
        "}"
        :: "r"(d), "l"(ad), "l"(bd), "r"(idesc), "r"(acc) : "memory");
}

// idesc: dtype F32 (1<<4), atype TF32 (2<<7), btype TF32 (2<<10), N/8<<17, M/16<<24
static constexpr uint32_t IDESC_TF32_128x256 =
    (1u << 4) | (2u << 7) | (2u << 10) | (32u << 17) | (8u << 24);

// ---------------------------------------------------------------------------
// Shared mainloop (software-pipelined A; optional cluster-2 multicast B).
// MC: both cluster CTAs bulk-copy HALF the B chunk each and multicast it to
// both CTAs; commits are multicast so buffer-reuse waits cover the PEER's
// MMAs too (its DMA writes into our buffers). mma-done mbars must be
// initialized with count 2 in MC mode (1 otherwise).
// SMEM header: [0] tmem ptr, [8],[16] MMA-done mbars, [24],[32] B-load mbars.
// ---------------------------------------------------------------------------
template <int NT, int NC, bool RS, bool MC>
__device__ __forceinline__ void tc_mainloop(const float* __restrict__ A,
                                            const float* __restrict__ Wp,
                                            uint32_t sb, uint32_t tb, size_t bm,
                                            int& ph0, int& ph1, float* rs,
                                            uint32_t rank)
{
    constexpr int      NTOT   = NT * 256;
    constexpr int      K      = NC * 32;
    constexpr int      STAGE  = (128 + NTOT) * 128;
    constexpr uint32_t BBYTES = NTOT * 128;
    const int tid = threadIdx.x;
    const int wid = tid >> 5;
    const int r0  = tid >> 3;          // rows r0, r0+32, r0+64, r0+96
    const int q   = tid & 7;

    const uint32_t aBase0 = sb + 1024;
    const uint32_t bBase0 = aBase0 + 128 * 128;

    int phl0 = 0, phl1 = 0;

    // Prefetch chunk 0's A tile
    float4 av[4];
#pragma unroll
    for (int i = 0; i < 4; i++)
        av[i] = *(const float4*)(A + (bm + r0 + 32 * i) * (size_t)K + q * 4);

    for (int c = 0; c < NC; c++) {
        const int      buf = c & 1;
        const uint32_t aB  = aBase0 + buf * STAGE;
        const uint32_t bB  = bBase0 + buf * STAGE;

        // Buffer reuse guard: MMAs of chunk c-2 on this buffer must be done
        // (in MC mode this includes the peer CTA's MMAs, via multicast commit).
        if (c >= 2) {
            if (buf == 0) { MBARRIER_WAIT_PARITY(sb + 8,  ph0); ph0 ^= 1; }
            else          { MBARRIER_WAIT_PARITY(sb + 16, ph1); ph1 ^= 1; }
        }

        // B chunk DMA
        if (tid == 0) {
            MBARRIER_EXPECT_TX(sb + 24 + buf * 8, BBYTES);
            if (MC) {
                constexpr uint32_t HALF = BBYTES / 2;
                CP_ASYNC_BULK_G2S_MC(bB + rank * HALF,
                                     (const char*)Wp + (size_t)c * BBYTES + rank * HALF,
                                     HALF, sb + 24 + buf * 8, 0x3);
            } else {
                CP_ASYNC_BULK_G2S(bB, (const char*)Wp + (size_t)c * BBYTES, BBYTES,
                                  sb + 24 + buf * 8);
            }
        }

        // Store prefetched A (rna tf32 round) and prefetch chunk c+1
#pragma unroll
        for (int i = 0; i < 4; i++) {
            uint32_t x = rna_tf32(av[i].x), y = rna_tf32(av[i].y),
                     z = rna_tf32(av[i].z), w = rna_tf32(av[i].w);
            uint32_t dst = aB + sw128((uint32_t)((r0 + 32 * i) * 128 + q * 16));
            asm volatile("st.shared.v4.b32 [%0], {%1,%2,%3,%4};"
                         :: "r"(dst), "r"(x), "r"(y), "r"(z), "r"(w) : "memory");
        }
        if (c + 1 < NC) {
#pragma unroll
            for (int i = 0; i < 4; i++)
                av[i] = *(const float4*)(A + (bm + r0 + 32 * i) * (size_t)K +
                                         (c + 1) * 32 + q * 4);
        }
        TCGEN05_FENCE_BEFORE();
        __syncthreads();

        // Optional per-row sums of staged (rounded) A — thread t owns row t
        if (RS && tid < 128) {
            float acc = 0.f;
#pragma unroll
            for (int qq = 0; qq < 8; qq++) {
                uint32_t addr = aB + sw128((uint32_t)(tid * 128 + qq * 16));
                float x, y, z, w;
                asm volatile("ld.shared.v4.f32 {%0,%1,%2,%3}, [%4];"
                             : "=f"(x), "=f"(y), "=f"(z), "=f"(w) : "r"(addr));
                acc += x + y + z + w;
            }
            *rs += acc;
        }

        if (wid == 0) {
            TCGEN05_FENCE_AFTER();
            const int phl = (buf == 0) ? phl0 : phl1;
            if (elect_one()) {
                MBARRIER_WAIT_PARITY(sb + 24 + buf * 8, phl);   // B landed (both halves)
                const uint64_t ad  = sw128_desc(aB);
                const uint64_t bd0 = sw128_desc(bB);
                const uint64_t bd1 = sw128_desc(bB + 256 * 128);
#pragma unroll
                for (int s = 0; s < 4; s++) {
                    const uint32_t acc = (c > 0 || s > 0) ? 1u : 0u;
                    mma_tf32_ss(tb,       ad + 2 * s, bd0 + 2 * s, IDESC_TF32_128x256, acc);
                    if (NT == 2)
                        mma_tf32_ss(tb + 256, ad + 2 * s, bd1 + 2 * s, IDESC_TF32_128x256, acc);
                }
                if (MC) TCGEN05_COMMIT_MC(sb + 8 + buf * 8, 0x3);
                else    TCGEN05_COMMIT(sb + 8 + buf * 8);
            }
            if (buf == 0) phl0 ^= 1; else phl1 ^= 1;
        }
    }
}
#endif  // HAS_TC

// ---------------------------------------------------------------------------
// Generic GEMM with split-destination epilogue (8-warp, LDTM pair-batched).
//   cols 0..255   -> C0[r*ldc0 + c]       + bias0[c]
//   cols 256..511 -> C1[r*ldc1 + (c-256)] + bias1[c-256]   (NT==2 only)
// EPI 0: bias only.  EPI 2: fused gate — relu(D+bias) * relu(BN(A[r][c])).
// ---------------------------------------------------------------------------
template <int NT, int NC, int EPI>
__global__ void __launch_bounds__(256, 1)
tc_gemm_kernel(const float* __restrict__ A, const float* __restrict__ Wp,
               const float* __restrict__ bias0, const float* __restrict__ bias1,
               float* __restrict__ C0, int ldc0, float* __restrict__ C1, int ldc1,
               const float* __restrict__ mean, const float* __restrict__ rstd,
               const float* __restrict__ gamma, const float* __restrict__ beta)
{
    constexpr int NTOT = NT * 256;
    constexpr int K    = NC * 32;

#if HAS_TC
    extern __shared__ __align__(1024) char smem[];
    const uint32_t sb  = smem_u32(smem);
    const int      tid = threadIdx.x;
    const int      wid = tid >> 5, lane = tid & 31;
    const size_t   bm  = (size_t)blockIdx.x * 128;

    if (wid == 0) TCGEN05_ALLOC(sb, 512);
    if (tid == 0) {
        MBARRIER_INIT(sb + 8, 1);  MBARRIER_INIT(sb + 16, 1);
        MBARRIER_INIT(sb + 24, 1); MBARRIER_INIT(sb + 32, 1);
    }
    __syncthreads();
    uint32_t tb;
    asm volatile("ld.shared.b32 %0, [%1];" : "=r"(tb) : "r"(sb));

    int ph0 = 0, ph1 = 0;
    float rs_dummy = 0.f;
    tc_mainloop<NT, NC, false, false>(A, Wp, sb, tb, bm, ph0, ph1, &rs_dummy, 0);

    MBARRIER_WAIT_PARITY(sb + 8,  ph0);
    MBARRIER_WAIT_PARITY(sb + 16, ph1);
    TCGEN05_FENCE_AFTER();

    // 8-warp epilogue, pair-batched LDTM: warp w covers groups [(w>>2)*NT*4, +NT*4)
    {
        const size_t row = bm + (size_t)(wid & 3) * 32 + lane;
        const int    g0  = (wid >> 2) * (NT * 4);
#pragma unroll
        for (int gi = 0; gi < NT * 4; gi += 2) {
            uint32_t ra[32], rb[32];
            TCGEN05_LD_32X32B_X32(ra, tb + (g0 + gi) * 32);
            TCGEN05_LD_32X32B_X32(rb, tb + (g0 + gi + 1) * 32);
            TCGEN05_WAIT_LD();
#pragma unroll
            for (int h = 0; h < 2; h++) {
                const uint32_t* r = h ? rb : ra;
                const int c0g = (g0 + gi + h) * 32;
                float* const base = (c0g < 256) ? (C0 + row * (size_t)ldc0 + c0g)
                                                : (C1 + row * (size_t)ldc1 + (c0g - 256));
                const float* const bb = (c0g < 256) ? (bias0 + c0g) : (bias1 + (c0g - 256));
#pragma unroll
                for (int j = 0; j < 32; j += 4) {
                    float4 o;
                    o.x = __uint_as_float(r[j + 0]) + bb[j + 0];
                    o.y = __uint_as_float(r[j + 1]) + bb[j + 1];
                    o.z = __uint_as_float(r[j + 2]) + bb[j + 2];
                    o.w = __uint_as_float(r[j + 3]) + bb[j + 3];
                    if (EPI == 2) {
                        const int c = c0g + j;
                        float4 x = *(const float4*)(A + row * (size_t)K + c);
                        o.x = fmaxf(o.x, 0.f) *
                              fmaxf(gamma[c+0]*(x.x-mean[c+0])*rstd[c+0]+beta[c+0], 0.f);
                        o.y = fmaxf(o.y, 0.f) *
                              fmaxf(gamma[c+1]*(x.y-mean[c+1])*rstd[c+1]+beta[c+1], 0.f);
                        o.z = fmaxf(o.z, 0.f) *
                              fmaxf(gamma[c+2]*(x.z-mean[c+2])*rstd[c+2]+beta[c+2], 0.f);
                        o.w = fmaxf(o.w, 0.f) *
                              fmaxf(gamma[c+3]*(x.w-mean[c+3])*rstd[c+3]+beta[c+3], 0.f);
                    }
                    *(float4*)(base + j) = o;
                }
            }
        }
        TCGEN05_FENCE_BEFORE();
    }
    __syncthreads();
    if (wid == 0) { TCGEN05_RELINQ(); TCGEN05_DEALLOC(tb, 512); }

#else  // ----- generic fallback (correctness-only; never runs on sm_103a) ----
    const int    tid = threadIdx.x;
    const size_t bm  = (size_t)blockIdx.x * 128;
    for (int idx = tid; idx < 128 * NTOT; idx += 256) {
        const size_t row = bm + (idx / NTOT);
        const int    c   = idx % NTOT;
        float acc = (c < 256) ? bias0[c] : bias1[c - 256];
        for (int k = 0; k < K; k++)
            acc = fmaf(A[row * (size_t)K + k], w_packed(Wp, NTOT, c, k), acc);
        if (EPI == 2) {
            float x = A[row * (size_t)K + c];
            acc = fmaxf(acc, 0.f) * fmaxf(gamma[c]*(x-mean[c])*rstd[c]+beta[c], 0.f);
        }
        if (c < 256) C0[row * (size_t)ldc0 + c] = acc;
        else         C1[row * (size_t)ldc1 + (c - 256)] = acc;
    }
#endif
}

// ---------------------------------------------------------------------------
// Fused KV-projection + attention kernel, cluster-2 multicast B.
// ---------------------------------------------------------------------------
__global__ void __launch_bounds__(256, 1) __cluster_dims__(2, 1, 1)
kv_attn_kernel(const float* __restrict__ nbr, const float* __restrict__ Wp,
               const float* __restrict__ Q, const float* __restrict__ bk,
               const float* __restrict__ bv, float* __restrict__ ctx)
{
#if HAS_TC
    extern __shared__ __align__(1024) char smem[];
    const uint32_t sb   = smem_u32(smem);
    const int      tid  = threadIdx.x;
    const int      wid  = tid >> 5, lane = tid & 31;
    const size_t   bm   = (size_t)blockIdx.x * 128;
    const uint32_t rank = cluster_rank();

    if (wid == 0) TCGEN05_ALLOC(sb, 512);
    if (tid == 0) {
        // mma-done barriers: 2 arrivals (own + peer multicast commits)
        MBARRIER_INIT(sb + 8, 2);  MBARRIER_INIT(sb + 16, 2);
        MBARRIER_INIT(sb + 24, 1); MBARRIER_INIT(sb + 32, 1);
    }
    __syncthreads();
    // All cluster mbarriers must be live before any multicast targets them
    CLUSTER_SYNC();

    uint32_t tb;
    asm volatile("ld.shared.b32 %0, [%1];" : "=r"(tb) : "r"(sb));

    int ph0 = 0, ph1 = 0;
    float rs = 0.f;   // row-sum of this thread's A row (tid < 128: row bm+tid)
    tc_mainloop<2, 8, true, true>(nbr, Wp, sb, tb, bm, ph0, ph1, &rs, rank);

    MBARRIER_WAIT_PARITY(sb + 8,  ph0);
    MBARRIER_WAIT_PARITY(sb + 16, ph1);
    TCGEN05_FENCE_AFTER();

    // Epilogue smem layout (bytes from dynamic smem base):
    //   1024 : qs[4][256]  5120 : bkq_s[4]  5248 : e_part[8][32]
    //   6272 : att_s[4][32]  7168 : tr[8][32*33]
    float* const qs_all  = (float*)(smem + 1024);
    float* const bkq_s   = (float*)(smem + 5120);
    float* const e_part  = (float*)(smem + 5248);
    float* const att_s   = (float*)(smem + 6272);
    float* const tr_all  = (float*)(smem + 7168);

    // Phase 0: warps 0-3 stage node's q and fold bk.q
    if (wid < 4) {
        const size_t node = (size_t)blockIdx.x * 4 + wid;
        float* qs = qs_all + wid * 256;
        float4 q0 = *(const float4*)(Q + node * 256 + lane * 8);
        float4 q1 = *(const float4*)(Q + node * 256 + lane * 8 + 4);
        *(float4*)(qs + lane * 8)     = q0;
        *(float4*)(qs + lane * 8 + 4) = q1;
        float4 b0 = *(const float4*)(bk + lane * 8);
        float4 b1 = *(const float4*)(bk + lane * 8 + 4);
        float bkq = q0.x*b0.x + q0.y*b0.y + q0.z*b0.z + q0.w*b0.w
                  + q1.x*b1.x + q1.y*b1.y + q1.z*b1.z + q1.w*b1.w;
#pragma unroll
        for (int o = 16; o; o >>= 1) bkq += __shfl_xor_sync(0xffffffffu, bkq, o);
        if (lane == 0) bkq_s[wid] = bkq;
    }
    __syncthreads();

    // Phase 1: all 8 warps — partial energies over 4 key groups (pair-batched)
    {
        const int    node = wid & 3;
        const int    gb   = (wid >> 2) * 4;
        const float* qs   = qs_all + node * 256;
        float e = 0.f;
#pragma unroll
        for (int i = 0; i < 4; i += 2) {
            uint32_t ra[32], rb[32];
            TCGEN05_LD_32X32B_X32(ra, tb + (gb + i) * 32);
            TCGEN05_LD_32X32B_X32(rb, tb + (gb + i + 1) * 32);
            TCGEN05_WAIT_LD();
            const float* qp0 = qs + (gb + i) * 32;
            const float* qp1 = qs + (gb + i + 1) * 32;
#pragma unroll
            for (int j = 0; j < 32; j++) {
                e = fmaf(__uint_as_float(ra[j]), qp0[j], e);
                e = fmaf(__uint_as_float(rb[j]), qp1[j], e);
            }
        }
        e_part[wid * 32 + lane] = e;
    }
    __syncthreads();

    // Phase 2: warps 0-3 — combine, mask, softmax
    if (wid < 4) {
        float e = e_part[wid * 32 + lane] + e_part[(wid + 4) * 32 + lane] + bkq_s[wid];
        if (rs == 0.0f) e = 1e-12f;
        float m = e;
#pragma unroll
        for (int o = 16; o; o >>= 1) m = fmaxf(m, __shfl_xor_sync(0xffffffffu, m, o));
        float ex = expf(e - m);
        float s = ex;
#pragma unroll
        for (int o = 16; o; o >>= 1) s += __shfl_xor_sync(0xffffffffu, s, o);
        att_s[wid * 32 + lane] = ex / s;
    }
    __syncthreads();

    // Phase 3: all 8 warps — context over 4 value groups (pair-batched LDTM,
    // smem transpose per group)
    {
        const int    node = wid & 3;
        const int    gb   = (wid >> 2) * 4;
        const float  a    = att_s[node * 32 + lane];
        float* const tr   = tr_all + wid * (32 * 33);
        const size_t nidx = (size_t)blockIdx.x * 4 + node;
#pragma unroll
        for (int i = 0; i < 4; i += 2) {
            uint32_t ra[32], rb[32];
            TCGEN05_LD_32X32B_X32(ra, tb + 256 + (gb + i) * 32);
            TCGEN05_LD_32X32B_X32(rb, tb + 256 + (gb + i + 1) * 32);
            TCGEN05_WAIT_LD();
#pragma unroll
            for (int h = 0; h < 2; h++) {
                const uint32_t* r = h ? rb : ra;
                const int g = gb + i + h;
#pragma unroll
                for (int j = 0; j < 32; j++) tr[j * 33 + lane] = __uint_as_float(r[j]) * a;
                __syncwarp();
                float c = bv[g * 32 + lane];
                const float* trow = tr + lane * 33;
#pragma unroll
                for (int k = 0; k < 32; k++) c += trow[k];
                ctx[nidx * 256 + g * 32 + lane] = c;
                __syncwarp();
            }
        }
        TCGEN05_FENCE_BEFORE();
    }
    __syncthreads();
    if (wid == 0) { TCGEN05_RELINQ(); TCGEN05_DEALLOC(tb, 512); }
    // No CTA may exit while a peer's multicast into its SMEM could be in flight
    CLUSTER_SYNC();

#else  // ----- generic fallback (correctness-only; never runs on sm_103a) ----
    const int    tid = threadIdx.x;
    const size_t bm  = (size_t)blockIdx.x * 128;
    __shared__ float att_f[128];

    if (tid < 128) {
        const size_t row  = bm + tid;
        const size_t node = row >> 5;
        float rsum = 0.f;
        for (int i = 0; i < DIN; i++) rsum += nbr[row * DIN + i];
        float e = 0.f;
        for (int d = 0; d < DOUT; d++) {
            float kd = bk[d];
            for (int i = 0; i < DIN; i++)
                kd = fmaf(nbr[row * DIN + i], w_packed(Wp, DCAT, d, i), kd);
            e = fmaf(kd, Q[node * DOUT + d], e);
        }
        if (rsum == 0.f) e = 1e-12f;
        float m = e;
        for (int o = 16; o; o >>= 1) m = fmaxf(m, __shfl_xor_sync(0xffffffffu, m, o));
        float ex = expf(e - m);
        float s = ex;
        for (int o = 16; o; o >>= 1) s += __shfl_xor_sync(0xffffffffu, s, o);
        att_f[tid] = ex / s;
    }
    __syncthreads();

    for (int idx = tid; idx < 4 * DOUT; idx += 256) {
        const int    ln   = idx >> 8;
        const int    d    = idx & 255;
        const size_t node = (size_t)blockIdx.x * 4 + ln;
        float c = bv[d];
        for (int k = 0; k < KNBR; k++) {
            const float* xr = nbr + (node * KNBR + k) * (size_t)DIN;
            float vd = 0.f;
            for (int i = 0; i < DIN; i++)
                vd = fmaf(xr[i], w_packed(Wp, DCAT, 256 + d, i), vd);
            c = fmaf(att_f[ln * 32 + k], vd, c);
        }
        ctx[node * DOUT + d] = c;
    }
#endif
}

// ---------------------------------------------------------------------------
// Fused weight packing: all 4 matrices in one launch. Block b handles one
// (matrix, 32-row tile, 32-col chunk). tf32-round into swizzled images.
// Blocks: Wqio 128, Wkv 128, Wno 64, Wg 256  -> 576 total.
// ---------------------------------------------------------------------------
__global__ void __launch_bounds__(256)
pack_all_kernel(const float* __restrict__ Wq,  const float* __restrict__ Wio,
                const float* __restrict__ Wk,  const float* __restrict__ Wv,
                const float* __restrict__ Wno, const float* __restrict__ Wg,
                float* __restrict__ Wqio_d, float* __restrict__ Wkv_d,
                float* __restrict__ Wno_d,  float* __restrict__ Wg_d)
{
    int b = blockIdx.x;
    const float *s0, *s1;
    float* dst;
    int K, ntot, rt, ct;
    if (b < 128)      { s0 = Wq;  s1 = Wio;           dst = Wqio_d; K = 256; ntot = 512; rt = b >> 3;  ct = b & 7; }
    else if (b < 256) { b -= 128; s0 = Wk;  s1 = Wv;   dst = Wkv_d; K = 256; ntot = 512; rt = b >> 3;  ct = b & 7; }
    else if (b < 320) { b -= 256; s0 = Wno; s1 = Wno;  dst = Wno_d; K = 256; ntot = 256; rt = b >> 3;  ct = b & 7; }
    else              { b -= 320; s0 = Wg;  s1 = Wg + 256 * 512; dst = Wg_d; K = 512; ntot = 512; rt = b >> 4; ct = b & 15; }

    const int r = rt * 32 + (threadIdx.x >> 3);
    const int q = threadIdx.x & 7;
    const float* src = (r < 256) ? (s0 + (size_t)r * K) : (s1 + (size_t)(r - 256) * K);
    float4 v = *(const float4*)(src + ct * 32 + q * 4);
    float4 o;
    o.x = __uint_as_float(rna_tf32(v.x));
    o.y = __uint_as_float(rna_tf32(v.y));
    o.z = __uint_as_float(rna_tf32(v.z));
    o.w = __uint_as_float(rna_tf32(v.w));
    *(float4*)(dst + (size_t)ct * ((size_t)ntot * 32) +
               (sw128((uint32_t)(r * 128 + q * 16)) >> 2)) = o;
}

// ---------------------------------------------------------------------------
// BatchNorm statistics (deterministic two-phase)
// ---------------------------------------------------------------------------
__global__ void __launch_bounds__(256)
bn_partial_kernel(const float* __restrict__ ob, float* __restrict__ psum,
                  float* __restrict__ psq)
{
    const int b = blockIdx.x, t = threadIdx.x;   // 256 blocks x 64 rows
    float s0 = 0, s1 = 0, q0 = 0, q1 = 0;
    for (int r = 0; r < 64; r++) {
        const float* row = ob + ((size_t)b * 64 + r) * DCAT;
        float x0 = row[t], x1 = row[t + 256];
        s0 += x0; q0 += x0 * x0;
        s1 += x1; q1 += x1 * x1;
    }
    psum[b * DCAT + t]       = s0;
    psum[b * DCAT + t + 256] = s1;
    psq[b * DCAT + t]        = q0;
    psq[b * DCAT + t + 256]  = q1;
}

__global__ void bn_final_kernel(const float* __restrict__ psum, const float* __restrict__ psq,
                                float* __restrict__ mean, float* __restrict__ rstd)
{
    const int c = blockIdx.x * 256 + threadIdx.x;
    float s = 0, q = 0;
    for (int b = 0; b < 256; b++) { s += psum[b * DCAT + c]; q += psq[b * DCAT + c]; }
    float m = s / (float)N_NODES;
    float v = q / (float)N_NODES - m * m;
    mean[c] = m;
    rstd[c] = rsqrtf(v + 1e-5f);
}

// ---------------------------------------------------------------------------
// Launch
// ---------------------------------------------------------------------------
extern "C" void kernel_launch(void* const* d_in, const int* in_sizes, int n_in,
                              void* d_out, int out_size)
{
    const float* input = (const float*)d_in[0];
    const float* nbr   = (const float*)d_in[1];
    const float* Wq    = (const float*)d_in[2];
    const float* bq    = (const float*)d_in[3];
    const float* Wk    = (const float*)d_in[4];
    const float* bk    = (const float*)d_in[5];
    const float* Wv    = (const float*)d_in[6];
    const float* bv    = (const float*)d_in[7];
    const float* Wno   = (const float*)d_in[8];
    const float* bno   = (const float*)d_in[9];
    const float* Wio   = (const float*)d_in[10];
    const float* bio   = (const float*)d_in[11];
    const float* Wg    = (const float*)d_in[12];
    const float* bg    = (const float*)d_in[13];
    const float* gamma = (const float*)d_in[14];
    const float* beta  = (const float*)d_in[15];
    float* out = (float*)d_out;

    float *Qp, *ctxp, *obp, *Wqiop, *Wkvp, *Wnop, *Wgp;
    float *psump, *psqp, *meanp, *rstdp;
    cudaGetSymbolAddress((void**)&Qp,    g_Q);
    cudaGetSymbolAddress((void**)&ctxp,  g_ctx);
    cudaGetSymbolAddress((void**)&obp,   g_ob);
    cudaGetSymbolAddress((void**)&Wqiop, g_Wqio_pk);
    cudaGetSymbolAddress((void**)&Wkvp,  g_Wkv_pk);
    cudaGetSymbolAddress((void**)&Wnop,  g_Wno_pk);
    cudaGetSymbolAddress((void**)&Wgp,   g_Wg_pk);
    cudaGetSymbolAddress((void**)&psump, g_psum);
    cudaGetSymbolAddress((void**)&psqp,  g_psq);
    cudaGetSymbolAddress((void**)&meanp, g_mean);
    cudaGetSymbolAddress((void**)&rstdp, g_rstd);

    // Dynamic SMEM: 1024 header + 2 buffers of (128+NTOT)*128 bytes
    const int SMEM1 = 1024 + 2 * (128 + 256) * 128;   //  99328
    const int SMEM2 = 1024 + 2 * (128 + 512) * 128;   // 164864
    cudaFuncSetAttribute(tc_gemm_kernel<2, 8,  0>, cudaFuncAttributeMaxDynamicSharedMemorySize, SMEM2);
    cudaFuncSetAttribute(tc_gemm_kernel<1, 8,  0>, cudaFuncAttributeMaxDynamicSharedMemorySize, SMEM1);
    cudaFuncSetAttribute(tc_gemm_kernel<2, 16, 2>, cudaFuncAttributeMaxDynamicSharedMemorySize, SMEM2);
    cudaFuncSetAttribute(kv_attn_kernel,           cudaFuncAttributeMaxDynamicSharedMemorySize, SMEM2);

    // Pack all weights in one launch (tf32-rounded swizzled images)
    pack_all_kernel<<<576, 256>>>(Wq, Wio, Wk, Wv, Wno, Wg, Wqiop, Wkvp, Wnop, Wgp);

    // fused Q + self projections: [queries | self_out] = input @ [Wq;Wio]^T
    tc_gemm_kernel<2, 8, 0><<<N_NODES / 128, 256, SMEM2>>>(
        input, Wqiop, bq, bio, Qp, DOUT, obp, DCAT,
        nullptr, nullptr, nullptr, nullptr);

    // fused: keys|values projection + masked softmax attention -> context
    // (cluster-2 cooperative multicast of the shared B tiles)
    kv_attn_kernel<<<NROWS / 128, 256, SMEM2>>>(nbr, Wkvp, Qp, bk, bv, ctxp);

    // neigh_out = context @ Wno^T + bno -> output[:, 256:512]
    tc_gemm_kernel<1, 8, 0><<<N_NODES / 128, 256, SMEM1>>>(
        ctxp, Wnop, bno, bno, obp + 256, DCAT, nullptr, 0,
        nullptr, nullptr, nullptr, nullptr);

    // BatchNorm statistics (needed before fused gate epilogue)
    bn_partial_kernel<<<256, 256>>>(obp, psump, psqp);
    bn_final_kernel<<<2, 256>>>(psump, psqp, meanp, rstdp);

    // gate GEMM with fused epilogue: out = relu(ob@Wg^T+bg) * relu(BN(ob))
    tc_gemm_kernel<2, 16, 2><<<N_NODES / 128, 256, SMEM2>>>(
        obp, Wgp, bg, bg + 256, out, DCAT, out + 256, DCAT,
        meanp, rstdp, gamma, beta);
}